// round 3
// baseline (speedup 1.0000x reference)
#include <cuda_runtime.h>
#include <cstdint>

#define T_STEPS 256
#define BATCH   64
#define INDIM   1024
#define HID     1024
#define G4      4096
#define NCTA2   128   // recurrent grid (<= #SMs, all co-resident)
#define UPC     8     // hidden units per recurrent CTA (128*8 = 1024)

// ---------------- scratch (static device globals; no allocs allowed) --------
__device__ float    g_xg[(size_t)T_STEPS * BATCH * G4];  // 256 MiB input projection
__device__ float    g_h[2][BATCH * HID];                 // double-buffered hidden state
__device__ unsigned g_bar_cnt;
__device__ unsigned g_bar_gen;

// ---------------- grid-wide barrier (sense via generation counter) ----------
__device__ __forceinline__ void grid_barrier(unsigned nctas) {
    __syncthreads();
    __threadfence();
    if (threadIdx.x == 0) {
        unsigned gen = *(volatile unsigned*)&g_bar_gen;
        unsigned t = atomicAdd(&g_bar_cnt, 1u);
        if (t == nctas - 1u) {
            *(volatile unsigned*)&g_bar_cnt = 0u;
            __threadfence();
            atomicAdd(&g_bar_gen, 1u);
        } else {
            while (*(volatile unsigned*)&g_bar_gen == gen) { __nanosleep(64); }
        }
        __threadfence();
    }
    __syncthreads();
}

// ---------------- Phase 1: xg = (x * W_ih^T + b_ih) + b_hh ------------------
// EXACT ORDER CONTRACT (matches XLA:CPU/Eigen): per output element, a single
// fp32 accumulator, strictly sequential fused-FMA over k = 0..1023 ascending,
// then + b_ih, then + b_hh (each a separate fp32 rounding).
#define BM 128
#define BN 128
#define BK 16

__global__ void __launch_bounds__(256, 2) gemm_xproj(
    const float* __restrict__ x, const float* __restrict__ Wih,
    const float* __restrict__ bih, const float* __restrict__ bhh)
{
    __shared__ float As[BK][132];
    __shared__ float Bs[BK][132];

    const int m0  = blockIdx.y * BM;
    const int n0  = blockIdx.x * BN;
    const int tid = threadIdx.x;
    const int tm  = tid >> 4;       // 0..15
    const int tn  = tid & 15;       // 0..15
    const int lk  = tid & 15;       // k lane for tile loads
    const int lr  = tid >> 4;       // row lane for tile loads

    float acc[8][8];
#pragma unroll
    for (int i = 0; i < 8; i++)
#pragma unroll
        for (int j = 0; j < 8; j++) acc[i][j] = 0.0f;

    for (int k0 = 0; k0 < INDIM; k0 += BK) {
#pragma unroll
        for (int p = 0; p < 8; p++) {
            int m = lr + p * 16;
            As[lk][m] = x[(size_t)(m0 + m) * INDIM + k0 + lk];
        }
#pragma unroll
        for (int p = 0; p < 8; p++) {
            int n = lr + p * 16;
            Bs[lk][n] = Wih[(size_t)(n0 + n) * INDIM + k0 + lk];
        }
        __syncthreads();

        // strictly sequential over k (ascending), single accumulator, FFMA
#pragma unroll
        for (int k = 0; k < BK; k++) {
            float4 a0 = *(const float4*)&As[k][tm * 8];
            float4 a1 = *(const float4*)&As[k][tm * 8 + 4];
            float4 b0 = *(const float4*)&Bs[k][tn * 8];
            float4 b1 = *(const float4*)&Bs[k][tn * 8 + 4];
            float av[8] = {a0.x, a0.y, a0.z, a0.w, a1.x, a1.y, a1.z, a1.w};
            float bv[8] = {b0.x, b0.y, b0.z, b0.w, b1.x, b1.y, b1.z, b1.w};
#pragma unroll
            for (int i = 0; i < 8; i++)
#pragma unroll
                for (int j = 0; j < 8; j++)
                    acc[i][j] = __fmaf_rn(av[i], bv[j], acc[i][j]);
        }
        __syncthreads();
    }

    // epilogue: (acc + b_ih) + b_hh  — two separate rounded adds, ref order
    float bi[8], bh[8];
#pragma unroll
    for (int j = 0; j < 8; j++) {
        int n = n0 + tn * 8 + j;
        bi[j] = bih[n];
        bh[j] = bhh[n];
    }
#pragma unroll
    for (int i = 0; i < 8; i++) {
        float v[8];
#pragma unroll
        for (int j = 0; j < 8; j++)
            v[j] = __fadd_rn(__fadd_rn(acc[i][j], bi[j]), bh[j]);
        size_t row = (size_t)(m0 + tm * 8 + i) * G4 + (n0 + tn * 8);
        *(float4*)&g_xg[row]     = make_float4(v[0], v[1], v[2], v[3]);
        *(float4*)&g_xg[row + 4] = make_float4(v[4], v[5], v[6], v[7]);
    }
}

// ---------------- Phase 2: persistent recurrent kernel ----------------------
// EXACT ORDER CONTRACT: hg = sequential fused-FMA over k = 0..1023 ascending
// starting from 0.0f; z = xg + hg (single rounded add). Gate/cell updates are
// exact small-integer arithmetic (no rounding).
__global__ void __launch_bounds__(256, 1) spiking_lstm_rec(
    const float* __restrict__ h0, const float* __restrict__ c0,
    const float* __restrict__ Whh, float* __restrict__ y)
{
    __shared__ float Ws[64][36];   // [k][col], col = gate*8 + u_local
    __shared__ float Hs[64][68];   // [k][b]
    __shared__ float Spk[64][33];  // [b][col]

    const int cta  = blockIdx.x;
    const int u0   = cta * UPC;
    const int tid  = threadIdx.x;
    const int col  = tid & 31;     // 0..31: gate = col/8, u_local = col%8
    const int bgrp = tid >> 5;     // 0..7: batch rows 8*bgrp..8*bgrp+7
    const int grow = (col >> 3) * HID + u0 + (col & 7);   // gate-axis index

    const int ub = tid & 7;
    const int bb = tid >> 3;       // 0..31
    float c_a = c0[(size_t)bb * HID + u0 + ub];
    float c_b = c0[(size_t)(bb + 32) * HID + u0 + ub];

    __stcg(&g_h[0][(size_t)bb * HID + u0 + ub],
           h0[(size_t)bb * HID + u0 + ub]);
    __stcg(&g_h[0][(size_t)(bb + 32) * HID + u0 + ub],
           h0[(size_t)(bb + 32) * HID + u0 + ub]);
    grid_barrier(NCTA2);

    // tile-load lanes
    const int lb = tid & 63;              // h-load: batch row
    const int lk = (tid >> 6) * 16;       // h-load: k offset (0,16,32,48)
    const int wcol = tid & 31;            // W-load: column owner
    const int wk   = (tid >> 5) * 8;      // W-load: k offset (0..56)
    const int wg   = (wcol >> 3) * HID + u0 + (wcol & 7);

    for (int s = 0; s < T_STEPS; s++) {
        const float* __restrict__ hprev = g_h[s & 1];
        float* __restrict__ hnext = g_h[(s + 1) & 1];

        // xg values (added AFTER the k-sum, per reference order)
        float xgv[8];
        {
            size_t base = (size_t)s * BATCH * G4 + grow;
#pragma unroll
            for (int r = 0; r < 8; r++)
                xgv[r] = g_xg[base + (size_t)(bgrp * 8 + r) * G4];
        }

        // hg = h @ W_hh^T, sequential k from 0
        float acc[8];
#pragma unroll
        for (int r = 0; r < 8; r++) acc[r] = 0.0f;

        for (int kc = 0; kc < HID; kc += 64) {
            const float* hp = hprev + (size_t)lb * HID + kc + lk;
#pragma unroll
            for (int j = 0; j < 16; j++) Hs[lk + j][lb] = __ldcg(&hp[j]);

            const float* wp = Whh + (size_t)wg * HID + kc + wk;
#pragma unroll
            for (int j = 0; j < 8; j++) Ws[wk + j][wcol] = wp[j];
            __syncthreads();

#pragma unroll 16
            for (int k = 0; k < 64; k++) {
                float w = Ws[k][col];
                float4 p = *(const float4*)&Hs[k][bgrp * 8];
                float4 q = *(const float4*)&Hs[k][bgrp * 8 + 4];
                acc[0] = __fmaf_rn(p.x, w, acc[0]);
                acc[1] = __fmaf_rn(p.y, w, acc[1]);
                acc[2] = __fmaf_rn(p.z, w, acc[2]);
                acc[3] = __fmaf_rn(p.w, w, acc[3]);
                acc[4] = __fmaf_rn(q.x, w, acc[4]);
                acc[5] = __fmaf_rn(q.y, w, acc[5]);
                acc[6] = __fmaf_rn(q.z, w, acc[6]);
                acc[7] = __fmaf_rn(q.w, w, acc[7]);
            }
            __syncthreads();
        }

        // z = xg + hg; spike
#pragma unroll
        for (int r = 0; r < 8; r++) {
            float z = __fadd_rn(xgv[r], acc[r]);
            Spk[bgrp * 8 + r][col] = (z >= 0.0f) ? 1.0f : 0.0f;
        }
        __syncthreads();

        // gate update: c' = f*c + i*g ; h' = o*c'   (exact integer math)
        {
            float i1 = Spk[bb][ub],      f1 = Spk[bb][8 + ub];
            float g1 = Spk[bb][16 + ub], o1 = Spk[bb][24 + ub];
            c_a = __fadd_rn(__fmul_rn(f1, c_a), __fmul_rn(i1, g1));
            float ha = __fmul_rn(o1, c_a);
            y[((size_t)s * BATCH + bb) * HID + u0 + ub] = ha;
            __stcg(&hnext[(size_t)bb * HID + u0 + ub], ha);

            float i2 = Spk[bb + 32][ub],      f2 = Spk[bb + 32][8 + ub];
            float g2 = Spk[bb + 32][16 + ub], o2 = Spk[bb + 32][24 + ub];
            c_b = __fadd_rn(__fmul_rn(f2, c_b), __fmul_rn(i2, g2));
            float hb = __fmul_rn(o2, c_b);
            y[((size_t)s * BATCH + bb + 32) * HID + u0 + ub] = hb;
            __stcg(&hnext[(size_t)(bb + 32) * HID + u0 + ub], hb);
        }

        grid_barrier(NCTA2);
    }
}

// ---------------- launch ----------------------------------------------------
extern "C" void kernel_launch(void* const* d_in, const int* in_sizes, int n_in,
                              void* d_out, int out_size) {
    const float* x   = (const float*)d_in[0];   // [T,B,I]
    const float* h0  = (const float*)d_in[1];   // [B,H]
    const float* c0  = (const float*)d_in[2];   // [B,H]
    const float* Wih = (const float*)d_in[3];   // [4H,I]
    const float* bih = (const float*)d_in[4];   // [4H]
    const float* Whh = (const float*)d_in[5];   // [4H,H]
    const float* bhh = (const float*)d_in[6];   // [4H]
    float* y = (float*)d_out;                   // [T,B,H]

    gemm_xproj<<<dim3(G4 / BN, (T_STEPS * BATCH) / BM), 256>>>(x, Wih, bih, bhh);
    spiking_lstm_rec<<<NCTA2, 256>>>(h0, c0, Whh, y);
}

// round 4
// speedup vs baseline: 2.1310x; 2.1310x over previous
#include <cuda_runtime.h>
#include <cstdint>

#define T_STEPS 256
#define BATCH   64
#define INDIM   1024
#define HID     1024
#define G4      4096
#define NCTA2   128   // recurrent grid, all co-resident (1 CTA/SM)
#define UPC     8     // hidden units per recurrent CTA
#define KC      128   // k-chunk for h staging

// ---------------- scratch (static device globals; no allocs allowed) --------
__device__ float    g_xg[(size_t)T_STEPS * BATCH * G4];  // 256 MiB input projection
__device__ float    g_h[2][HID][BATCH];                  // TRANSPOSED [k][b], double buffered
__device__ unsigned g_bar_cnt;
__device__ unsigned g_bar_gen;

// ---------------- grid-wide barrier (proven in round 3) ---------------------
__device__ __forceinline__ void grid_barrier(unsigned nctas) {
    __syncthreads();
    __threadfence();
    if (threadIdx.x == 0) {
        unsigned gen = *(volatile unsigned*)&g_bar_gen;
        unsigned t = atomicAdd(&g_bar_cnt, 1u);
        if (t == nctas - 1u) {
            *(volatile unsigned*)&g_bar_cnt = 0u;
            __threadfence();
            atomicAdd(&g_bar_gen, 1u);
        } else {
            while (*(volatile unsigned*)&g_bar_gen == gen) { __nanosleep(64); }
        }
        __threadfence();
    }
    __syncthreads();
}

// ---------------- cp.async helpers ------------------------------------------
__device__ __forceinline__ void cp_async_cg16(void* dst_smem, const void* src) {
    unsigned d = (unsigned)__cvta_generic_to_shared(dst_smem);
    asm volatile("cp.async.cg.shared.global [%0], [%1], 16;\n" :: "r"(d), "l"(src));
}
__device__ __forceinline__ void cp_async_commit() {
    asm volatile("cp.async.commit_group;\n");
}
template <int N>
__device__ __forceinline__ void cp_async_wait() {
    asm volatile("cp.async.wait_group %0;\n" :: "n"(N));
}

// ---------------- Phase 1: xg = (x * W_ih^T + b_ih) + b_hh ------------------
// EXACT ORDER CONTRACT: per output element, single fp32 accumulator,
// sequential fused-FMA over k = 0..1023 ascending, then +b_ih, then +b_hh.
// Double-buffered smem tiles, BK=8, one __syncthreads per K-iter.
#define BM 128
#define BN 128
#define BK 8

__global__ void __launch_bounds__(256, 2) gemm_xproj(
    const float* __restrict__ x, const float* __restrict__ Wih,
    const float* __restrict__ bih, const float* __restrict__ bhh)
{
    __shared__ float As[2][BK][132];
    __shared__ float Bs[2][BK][132];

    const int m0  = blockIdx.y * BM;
    const int n0  = blockIdx.x * BN;
    const int tid = threadIdx.x;
    const int tm  = tid >> 4;       // 0..15
    const int tn  = tid & 15;       // 0..15
    const int lk  = tid & 7;        // k lane for tile loads
    const int lr  = tid >> 3;       // row lane (0..31)

    float acc[8][8];
#pragma unroll
    for (int i = 0; i < 8; i++)
#pragma unroll
        for (int j = 0; j < 8; j++) acc[i][j] = 0.0f;

    float ra[4], rb[4];
#pragma unroll
    for (int p = 0; p < 4; p++) {
        ra[p] = x  [(size_t)(m0 + lr + p * 32) * INDIM + lk];
        rb[p] = Wih[(size_t)(n0 + lr + p * 32) * INDIM + lk];
    }

    for (int it = 0; it < INDIM / BK; it++) {
        const int buf = it & 1;
#pragma unroll
        for (int p = 0; p < 4; p++) {
            As[buf][lk][lr + p * 32] = ra[p];
            Bs[buf][lk][lr + p * 32] = rb[p];
        }
        __syncthreads();

        if (it + 1 < INDIM / BK) {
            const int k0 = (it + 1) * BK;
#pragma unroll
            for (int p = 0; p < 4; p++) {
                ra[p] = x  [(size_t)(m0 + lr + p * 32) * INDIM + k0 + lk];
                rb[p] = Wih[(size_t)(n0 + lr + p * 32) * INDIM + k0 + lk];
            }
        }

        // strictly sequential over k (ascending), single accumulator, FFMA
#pragma unroll
        for (int k = 0; k < BK; k++) {
            float4 a0 = *(const float4*)&As[buf][k][tm * 8];
            float4 a1 = *(const float4*)&As[buf][k][tm * 8 + 4];
            float4 b0 = *(const float4*)&Bs[buf][k][tn * 8];
            float4 b1 = *(const float4*)&Bs[buf][k][tn * 8 + 4];
            float av[8] = {a0.x, a0.y, a0.z, a0.w, a1.x, a1.y, a1.z, a1.w};
            float bv[8] = {b0.x, b0.y, b0.z, b0.w, b1.x, b1.y, b1.z, b1.w};
#pragma unroll
            for (int i = 0; i < 8; i++)
#pragma unroll
                for (int j = 0; j < 8; j++)
                    acc[i][j] = __fmaf_rn(av[i], bv[j], acc[i][j]);
        }
    }

    // epilogue: (acc + b_ih) + b_hh  — two separate rounded adds, ref order
    float bi[8], bh[8];
#pragma unroll
    for (int j = 0; j < 8; j++) {
        int n = n0 + tn * 8 + j;
        bi[j] = bih[n];
        bh[j] = bhh[n];
    }
#pragma unroll
    for (int i = 0; i < 8; i++) {
        float v[8];
#pragma unroll
        for (int j = 0; j < 8; j++)
            v[j] = __fadd_rn(__fadd_rn(acc[i][j], bi[j]), bh[j]);
        size_t row = (size_t)(m0 + tm * 8 + i) * G4 + (n0 + tn * 8);
        *(float4*)&g_xg[row]     = make_float4(v[0], v[1], v[2], v[3]);
        *(float4*)&g_xg[row + 4] = make_float4(v[4], v[5], v[6], v[7]);
    }
}

// ---------------- Phase 2: persistent recurrent kernel ----------------------
// W_hh slice persistent in dynamic smem (pitch-33); h transposed [k][b] in
// global, staged per 128-k chunk via cp.async.cg double buffering.
// EXACT ORDER CONTRACT: hg = sequential FFMA over k = 0..1023 ascending from
// 0.0f; z = xg + hg (single rounded add). Gate math exact (0/1 × integers).
#define SM_W    (HID * 33)            // 33792 floats
#define SM_HS   (KC * BATCH)          // 8192 floats per buffer
#define SM_SPK  (BATCH * 33)          // 2112 floats
#define SMEM_BYTES ((SM_W + 2 * SM_HS + SM_SPK) * 4)   // 209152 B

extern __shared__ float sm[];

__global__ void __launch_bounds__(256, 1) spiking_lstm_rec(
    const float* __restrict__ h0, const float* __restrict__ c0,
    const float* __restrict__ Whh, float* __restrict__ y)
{
    float* w_sm = sm;                       // w_sm[k*33 + col]
    float* hs   = sm + SM_W;                // hs[buf*SM_HS + k_local*64 + b]
    float* spk  = sm + SM_W + 2 * SM_HS;    // spk[b*33 + col]

    const int cta  = blockIdx.x;
    const int u0   = cta * UPC;
    const int tid  = threadIdx.x;
    const int col  = tid & 31;     // gate = col/8, u_local = col%8
    const int bgrp = tid >> 5;     // batch rows 8*bgrp..8*bgrp+7
    const int ub   = tid & 7;
    const int bb   = tid >> 3;     // 0..31

    // ---- load W_hh slice into persistent smem (one time) ----
    {
        const int wc  = tid >> 3;                         // col 0..31
        const int sub = tid & 7;
        const int wrow = (wc >> 3) * HID + u0 + (wc & 7); // W_hh row for col wc
        const float* wp = Whh + (size_t)wrow * HID;
        for (int k0 = sub * 4; k0 < HID; k0 += 32) {
            float4 v = *(const float4*)&wp[k0];
            w_sm[(k0 + 0) * 33 + wc] = v.x;
            w_sm[(k0 + 1) * 33 + wc] = v.y;
            w_sm[(k0 + 2) * 33 + wc] = v.z;
            w_sm[(k0 + 3) * 33 + wc] = v.w;
        }
    }

    // ---- init c and transposed h[0] ----
    float c_a = c0[(size_t)bb * HID + u0 + ub];
    float c_b = c0[(size_t)(bb + 32) * HID + u0 + ub];
    __stcg(&g_h[0][u0 + ub][bb],      h0[(size_t)bb * HID + u0 + ub]);
    __stcg(&g_h[0][u0 + ub][bb + 32], h0[(size_t)(bb + 32) * HID + u0 + ub]);
    grid_barrier(NCTA2);   // includes __syncthreads -> w_sm also ready

    for (int s = 0; s < T_STEPS; s++) {
        const float* __restrict__ hprev = &g_h[s & 1][0][0];

        // xg values (consumed at end of step; loads overlap all compute)
        float xgv[8];
        {
            size_t base = (size_t)s * BATCH * G4 + (size_t)((col >> 3) * HID + u0 + (col & 7));
#pragma unroll
            for (int r = 0; r < 8; r++)
                xgv[r] = g_xg[base + (size_t)(bgrp * 8 + r) * G4];
        }

        float acc[8];
#pragma unroll
        for (int r = 0; r < 8; r++) acc[r] = 0.0f;

        // prefetch chunk 0 (each thread copies 32 contiguous floats)
        {
            const float* src = hprev + tid * 32;
            float* dst = hs + tid * 32;
#pragma unroll
            for (int j = 0; j < 8; j++)
                cp_async_cg16(dst + j * 4, src + j * 4);
            cp_async_commit();
        }

        for (int ic = 0; ic < HID / KC; ic++) {
            if (ic + 1 < HID / KC) {
                // prefetch next chunk into alternate buffer
                const float* src = hprev + (ic + 1) * KC * BATCH + tid * 32;
                float* dst = hs + ((ic + 1) & 1) * SM_HS + tid * 32;
#pragma unroll
                for (int j = 0; j < 8; j++)
                    cp_async_cg16(dst + j * 4, src + j * 4);
                cp_async_commit();
                cp_async_wait<1>();   // chunk ic complete, ic+1 in flight
            } else {
                cp_async_wait<0>();
            }
            __syncthreads();

            const float* wk = w_sm + (ic * KC) * 33 + col;
            const float* hb = hs + (ic & 1) * SM_HS + bgrp * 8;
#pragma unroll 8
            for (int k = 0; k < KC; k++) {
                float w = wk[k * 33];
                float4 p = *(const float4*)&hb[k * 64];
                float4 q = *(const float4*)&hb[k * 64 + 4];
                acc[0] = __fmaf_rn(p.x, w, acc[0]);
                acc[1] = __fmaf_rn(p.y, w, acc[1]);
                acc[2] = __fmaf_rn(p.z, w, acc[2]);
                acc[3] = __fmaf_rn(p.w, w, acc[3]);
                acc[4] = __fmaf_rn(q.x, w, acc[4]);
                acc[5] = __fmaf_rn(q.y, w, acc[5]);
                acc[6] = __fmaf_rn(q.z, w, acc[6]);
                acc[7] = __fmaf_rn(q.w, w, acc[7]);
            }
            __syncthreads();   // protects buffer reuse by next prefetch
        }

        // z = xg + hg; spike
#pragma unroll
        for (int r = 0; r < 8; r++) {
            float z = __fadd_rn(xgv[r], acc[r]);
            spk[(bgrp * 8 + r) * 33 + col] = (z >= 0.0f) ? 1.0f : 0.0f;
        }
        __syncthreads();

        // gate update: c' = f*c + i*g ; h' = o*c'   (exact 0/1-integer math)
        {
            float* hnext = &g_h[(s + 1) & 1][0][0];

            float i1 = spk[bb * 33 + ub],      f1 = spk[bb * 33 + 8 + ub];
            float g1 = spk[bb * 33 + 16 + ub], o1 = spk[bb * 33 + 24 + ub];
            c_a = __fadd_rn(__fmul_rn(f1, c_a), __fmul_rn(i1, g1));
            float ha = __fmul_rn(o1, c_a);
            y[((size_t)s * BATCH + bb) * HID + u0 + ub] = ha;
            __stcg(&hnext[(size_t)(u0 + ub) * BATCH + bb], ha);

            float i2 = spk[(bb + 32) * 33 + ub],      f2 = spk[(bb + 32) * 33 + 8 + ub];
            float g2 = spk[(bb + 32) * 33 + 16 + ub], o2 = spk[(bb + 32) * 33 + 24 + ub];
            c_b = __fadd_rn(__fmul_rn(f2, c_b), __fmul_rn(i2, g2));
            float hb2 = __fmul_rn(o2, c_b);
            y[((size_t)s * BATCH + bb + 32) * HID + u0 + ub] = hb2;
            __stcg(&hnext[(size_t)(u0 + ub) * BATCH + bb + 32], hb2);
        }

        grid_barrier(NCTA2);
    }
}

// ---------------- launch ----------------------------------------------------
extern "C" void kernel_launch(void* const* d_in, const int* in_sizes, int n_in,
                              void* d_out, int out_size) {
    const float* x   = (const float*)d_in[0];   // [T,B,I]
    const float* h0  = (const float*)d_in[1];   // [B,H]
    const float* c0  = (const float*)d_in[2];   // [B,H]
    const float* Wih = (const float*)d_in[3];   // [4H,I]
    const float* bih = (const float*)d_in[4];   // [4H]
    const float* Whh = (const float*)d_in[5];   // [4H,H]
    const float* bhh = (const float*)d_in[6];   // [4H]
    float* y = (float*)d_out;                   // [T,B,H]

    cudaFuncSetAttribute(spiking_lstm_rec,
                         cudaFuncAttributeMaxDynamicSharedMemorySize, SMEM_BYTES);

    gemm_xproj<<<dim3(G4 / BN, (T_STEPS * BATCH) / BM), 256>>>(x, Wih, bih, bhh);
    spiking_lstm_rec<<<NCTA2, 256, SMEM_BYTES>>>(h0, c0, Whh, y);
}